// round 14
// baseline (speedup 1.0000x reference)
#include <cuda_runtime.h>
#include <cstdint>
#include <cmath>

#define NN   16000
#define EE   512000
#define FF   200
#define HH   256
#define NK0  10
#define NK1  5
#define NOUTC 16

// ---------------- device scratch (no allocations allowed) ----------------
__device__ float g_t0[NN*HH];
__device__ float g_t1[NN*HH];
__device__ float g_h1[NN*HH];
__device__ float g_h2[NN*HH];
__device__ float g_bottom[NN*HH];
__device__ int   g_srcs[EE];
__device__ float g_wn[EE];
__device__ int   g_rowptr[NN+1];
__device__ int   g_cnt[NN];
__device__ int   g_fill[NN];
__device__ float g_degw[NN];
__device__ float g_dinv[NN];
__device__ float g_selfn[NN];
__device__ int   g_a0[NN];
__device__ float g_xc0[NK0*HH];
__device__ float g_adj0[NK0*NK0];
__device__ float g_lat1[NK0*HH];
__device__ int   g_a1[NK0];
__device__ float g_lat2[NK1*HH];
__device__ float g_contrib[NK0*HH];

// ---------------- threefry2x32 (exact JAX semantics) ----------------
__host__ __device__ inline void tf2x32(uint32_t k0, uint32_t k1, uint32_t x0, uint32_t x1,
                                       uint32_t& o0, uint32_t& o1) {
  uint32_t ks2 = k0 ^ k1 ^ 0x1BD11BDAu;
#define ROTL32(x,d) (((x)<<(d))|((x)>>(32-(d))))
#define TFRND(r) { x0 += x1; x1 = ROTL32(x1,(r)); x1 ^= x0; }
  x0 += k0; x1 += k1;
  TFRND(13) TFRND(15) TFRND(26) TFRND(6)   x0 += k1;  x1 += ks2 + 1u;
  TFRND(17) TFRND(29) TFRND(16) TFRND(24)  x0 += ks2; x1 += k0 + 2u;
  TFRND(13) TFRND(15) TFRND(26) TFRND(6)   x0 += k0;  x1 += k1 + 3u;
  TFRND(17) TFRND(29) TFRND(16) TFRND(24)  x0 += k1;  x1 += ks2 + 4u;
  TFRND(13) TFRND(15) TFRND(26) TFRND(6)   x0 += ks2; x1 += k0 + 5u;
  o0 = x0; o1 = x1;
#undef TFRND
#undef ROTL32
}

__device__ __forceinline__ float gumbel_at(uint32_t k0, uint32_t k1, uint32_t t, uint32_t half) {
  uint32_t a, b, bits;
  if (t < half) { tf2x32(k0, k1, t, t + half, a, b); bits = a; }
  else          { tf2x32(k0, k1, t - half, t, a, b); bits = b; }
  float u01 = __uint_as_float((bits >> 9) | 0x3f800000u) - 1.0f;
  float u = fmaxf(1e-10f, u01 * (1.0f - 1e-10f) + 1e-10f);
  return -logf(-logf(u));
}

// ---------------- helpers ----------------
__device__ __forceinline__ float blockReduceSum256(float v, float* red) {
#pragma unroll
  for (int o = 16; o; o >>= 1) v += __shfl_xor_sync(0xffffffffu, v, o);
  int w = threadIdx.x >> 5;
  if ((threadIdx.x & 31) == 0) red[w] = v;
  __syncthreads();
  float r;
  if (threadIdx.x < 8) {
    r = red[threadIdx.x];
#pragma unroll
    for (int o = 4; o; o >>= 1) r += __shfl_xor_sync(0xffu, r, o);
    if (threadIdx.x == 0) red[0] = r;
  }
  __syncthreads();
  r = red[0];
  __syncthreads();
  return r;
}

__device__ __forceinline__ void mma_tf32(float c[4], const uint32_t a[4], const uint32_t b[2]) {
  asm volatile(
      "mma.sync.aligned.m16n8k8.row.col.f32.tf32.tf32.f32 "
      "{%0,%1,%2,%3}, {%4,%5,%6,%7}, {%8,%9}, {%0,%1,%2,%3};"
      : "+f"(c[0]), "+f"(c[1]), "+f"(c[2]), "+f"(c[3])
      : "r"(a[0]), "r"(a[1]), "r"(a[2]), "r"(a[3]), "r"(b[0]), "r"(b[1]));
}

__device__ __forceinline__ void cpasync16(uint32_t dst, const void* src, int src_bytes) {
  asm volatile("cp.async.cg.shared.global [%0], [%1], 16, %2;"
               :: "r"(dst), "l"(src), "r"(src_bytes));
}
__device__ __forceinline__ void cpasync_commit() {
  asm volatile("cp.async.commit_group;");
}
template <int N>
__device__ __forceinline__ void cpasync_wait() {
  asm volatile("cp.async.wait_group %0;" :: "n"(N));
}

// ---------------- graph preprocessing (split kernels, side stream) ----------------
__global__ void k_prep() {
  int i = blockIdx.x * blockDim.x + threadIdx.x;
  if (i < NN) { g_cnt[i] = 0; g_fill[i] = 0; g_degw[i] = 0.f; }
  if (i < NK0*HH) g_xc0[i] = 0.f;
  if (i < NK0*NK0) g_adj0[i] = 0.f;
}

__global__ void k_hist(const int* __restrict__ ei, const float* __restrict__ ew) {
  int e = blockIdx.x * blockDim.x + threadIdx.x;
  if (e >= EE) return;
  int d = ei[EE + e];
  atomicAdd(&g_cnt[d], 1);
  atomicAdd(&g_degw[d], ew[e]);
}

__global__ void k_scan_dinv() {
  __shared__ int totals[256];
  const int CH = 63;
  int t = threadIdx.x;
  int s0 = t * CH;
  int s1 = s0 + CH; if (s1 > NN) s1 = NN;
  int s = 0;
  for (int i = s0; i < s1; i++) s += g_cnt[i];
  totals[t] = s;
  __syncthreads();
  if (t == 0) {
    int run = 0;
    for (int i = 0; i < 256; i++) { int tmp = totals[i]; totals[i] = run; run += tmp; }
  }
  __syncthreads();
  int run = totals[t];
  for (int i = s0; i < s1; i++) { g_rowptr[i] = run; run += g_cnt[i]; }
  if (s0 < NN && s1 == NN) g_rowptr[NN] = run;
  for (int i = t; i < NN; i += 256) {
    float deg = g_degw[i] + 1.0f;
    float di = rsqrtf(deg);
    g_dinv[i] = di;
    g_selfn[i] = di * di;
  }
}

__global__ void k_scatter(const int* __restrict__ ei, const float* __restrict__ ew) {
  int e = blockIdx.x * blockDim.x + threadIdx.x;
  if (e >= EE) return;
  int s = ei[e], d = ei[EE + e];
  int pos = g_rowptr[d] + atomicAdd(&g_fill[d], 1);
  g_srcs[pos] = s;
  g_wn[pos] = ew[e] * g_dinv[s] * g_dinv[d];
}

// ---------------- tf32 tensor-core GEMM (BK=32, 3-stage cp.async pipeline) --------
// C = (accC ? C : 0) + sum_seg A_s @ B[rowoff_s:, :]
// epi: 0 none, 1 +bias, 2 +bias+relu
#define A_WORDS     4608
#define STAGE_WORDS 8832
#define GEMM_SMEM   (3 * STAGE_WORDS * 4)
__global__ void __launch_bounds__(256, 2) k_tf32gemm(
    const float* __restrict__ A0, const float* __restrict__ A1, const float* __restrict__ A2,
    int K0s, int K1s, int K2s, int lda0, int lda1, int lda2,
    const float* __restrict__ B, int ldb, float* __restrict__ C, int ldc,
    int epi, int accC, const float* __restrict__ bias)
{
  extern __shared__ uint32_t smem[];
  const int tid = threadIdx.x;
  const int lane = tid & 31, wid = tid >> 5;
  const int warpM = (wid >> 2) * 64, warpN = (wid & 3) * 32;
  const int bm = blockIdx.y * 128, bn = blockIdx.x * 128;

  const float* Aseg[3] = {A0, A1, A2};
  const int    Kseg[3] = {K0s, K1s, K2s};
  const int    Lseg[3] = {lda0, lda1, lda2};
  const int    Boff[3] = {0, K0s, K0s + K1s};

  float c[4][4][4];
#pragma unroll
  for (int mi = 0; mi < 4; mi++)
#pragma unroll
    for (int ni = 0; ni < 4; ni++)
#pragma unroll
      for (int q = 0; q < 4; q++) c[mi][ni][q] = 0.f;

  const int kc    = (tid & 7) * 4;
  const int arow0 = tid >> 3;
  const int bkrow = tid >> 5;
  const int bcol  = (tid & 31) * 4;
  const uint32_t sbase = (uint32_t)__cvta_generic_to_shared(smem);

  int T = 0;
#pragma unroll
  for (int s = 0; s < 3; s++) if (Kseg[s] > 0) T += (Kseg[s] + 31) / 32;

  int is = 0, ik = 0;
  auto issue_next = [&](int st) {
    const float* A = Aseg[is];
    const int lda = Lseg[is];
    const float* Bp = B + (size_t)Boff[is] * ldb;
    const int Krem = Kseg[is] - ik;
    uint32_t abase = sbase + (st * STAGE_WORDS) * 4;
    uint32_t bbase = sbase + (st * STAGE_WORDS + A_WORDS) * 4;
    int szA = (kc < Krem) ? 16 : 0;
#pragma unroll
    for (int u = 0; u < 4; u++) {
      int row = arow0 + u * 32;
      const float* src = szA ? (A + (size_t)(bm + row) * lda + ik + kc) : A;
      cpasync16(abase + (row * 36 + kc) * 4, src, szA);
    }
#pragma unroll
    for (int u = 0; u < 4; u++) {
      int krow = bkrow + u * 8;
      int szB = (krow < Krem) ? 16 : 0;
      const float* src = szB ? (Bp + (size_t)(ik + krow) * ldb + bn + bcol) : Bp;
      cpasync16(bbase + (krow * 132 + bcol) * 4, src, szB);
    }
    ik += 32;
    if (ik >= Kseg[is]) { is++; ik = 0; while (is < 3 && Kseg[is] == 0) is++; }
  };

  auto compute = [&](int st) {
    const uint32_t* Asb = smem + st * STAGE_WORDS;
    const uint32_t* Bsb = smem + st * STAGE_WORDS + A_WORDS;
#pragma unroll
    for (int kk = 0; kk < 4; kk++) {
      const int ks = kk * 8 + (lane & 3);
      const int rg = lane >> 2;
      uint32_t af[4][4];
#pragma unroll
      for (int mi = 0; mi < 4; mi++) {
        int row = warpM + mi * 16 + rg;
        af[mi][0] = Asb[row * 36 + ks];
        af[mi][1] = Asb[(row + 8) * 36 + ks];
        af[mi][2] = Asb[row * 36 + ks + 4];
        af[mi][3] = Asb[(row + 8) * 36 + ks + 4];
      }
      uint32_t bf[4][2];
#pragma unroll
      for (int ni = 0; ni < 4; ni++) {
        int col = warpN + ni * 8 + rg;
        bf[ni][0] = Bsb[ks * 132 + col];
        bf[ni][1] = Bsb[(ks + 4) * 132 + col];
      }
#pragma unroll
      for (int mi = 0; mi < 4; mi++)
#pragma unroll
        for (int ni = 0; ni < 4; ni++) mma_tf32(c[mi][ni], af[mi], bf[ni]);
    }
  };

  issue_next(0);
  cpasync_commit();
  if (T > 1) issue_next(1);
  cpasync_commit();
  for (int i = 0; i < T; i++) {
    if (i + 1 < T) cpasync_wait<1>(); else cpasync_wait<0>();
    __syncthreads();
    compute(i % 3);
    if (i + 2 < T) { issue_next((i + 2) % 3); cpasync_commit(); }
  }

  const int rg = lane >> 2, cg2 = (lane & 3) * 2;
#pragma unroll
  for (int mi = 0; mi < 4; mi++) {
    int raI = bm + warpM + mi * 16 + rg;
    int rbI = raI + 8;
#pragma unroll
    for (int ni = 0; ni < 4; ni++) {
      int cb = bn + warpN + ni * 8 + cg2;
      float v0 = c[mi][ni][0], v1 = c[mi][ni][1];
      float v2 = c[mi][ni][2], v3 = c[mi][ni][3];
      float* Ca = C + (size_t)raI * ldc + cb;
      float* Cb = C + (size_t)rbI * ldc + cb;
      if (accC) {
        float2 pa = *reinterpret_cast<float2*>(Ca);
        float2 pb = *reinterpret_cast<float2*>(Cb);
        v0 += pa.x; v1 += pa.y; v2 += pb.x; v3 += pb.y;
      }
      if (epi >= 1) { float b0 = bias[cb], b1 = bias[cb + 1]; v0 += b0; v1 += b1; v2 += b0; v3 += b1; }
      if (epi >= 2) { v0 = fmaxf(v0, 0.f); v1 = fmaxf(v1, 0.f); v2 = fmaxf(v2, 0.f); v3 = fmaxf(v3, 0.f); }
      *reinterpret_cast<float2*>(Ca) = make_float2(v0, v1);
      *reinterpret_cast<float2*>(Cb) = make_float2(v2, v3);
    }
  }
}

// ---------------- SpMM + self loop + bias + LayerNorm + ReLU (256 thr, 4 slices) --
__global__ void __launch_bounds__(256) k_spmm_ln_relu(
    const float* __restrict__ hin, float* __restrict__ out,
    const float* __restrict__ bias, const float* __restrict__ lng,
    const float* __restrict__ lnb)
{
  __shared__ float4 part[4][64];
  __shared__ float red[8];
  int v = blockIdx.x;
  int t = threadIdx.x;
  int fg = t & 63, es = t >> 6;
  int p0 = g_rowptr[v], p1 = g_rowptr[v + 1];
  float4 acc = make_float4(0.f, 0.f, 0.f, 0.f);
  if (es == 0) {
    float sn = g_selfn[v];
    float4 hv = *reinterpret_cast<const float4*>(hin + (size_t)v * HH + fg * 4);
    acc.x = hv.x * sn; acc.y = hv.y * sn; acc.z = hv.z * sn; acc.w = hv.w * sn;
  }
#pragma unroll 4
  for (int p = p0 + es; p < p1; p += 4) {
    int srow = g_srcs[p];
    float w = g_wn[p];
    float4 hv = *reinterpret_cast<const float4*>(hin + (size_t)srow * HH + fg * 4);
    acc.x = fmaf(hv.x, w, acc.x);
    acc.y = fmaf(hv.y, w, acc.y);
    acc.z = fmaf(hv.z, w, acc.z);
    acc.w = fmaf(hv.w, w, acc.w);
  }
  part[es][fg] = acc;
  __syncthreads();
  float4 a4 = make_float4(0.f, 0.f, 0.f, 0.f);
  float s = 0.f, sq = 0.f;
  if (t < 64) {
    float4 q0 = part[0][t], q1 = part[1][t], q2 = part[2][t], q3 = part[3][t];
    float4 b4 = *reinterpret_cast<const float4*>(bias + t * 4);
    a4.x = q0.x + q1.x + q2.x + q3.x + b4.x;
    a4.y = q0.y + q1.y + q2.y + q3.y + b4.y;
    a4.z = q0.z + q1.z + q2.z + q3.z + b4.z;
    a4.w = q0.w + q1.w + q2.w + q3.w + b4.w;
    s = a4.x + a4.y + a4.z + a4.w;
    sq = a4.x * a4.x + a4.y * a4.y + a4.z * a4.z + a4.w * a4.w;
  }
  float sum = blockReduceSum256(s, red);
  float sumsq = blockReduceSum256(sq, red);
  if (t < 64) {
    float mean = sum * (1.0f / HH);
    float var = sumsq * (1.0f / HH) - mean * mean;
    float rinv = rsqrtf(var + 1e-5f);
    float4 g4 = *reinterpret_cast<const float4*>(lng + t * 4);
    float4 l4 = *reinterpret_cast<const float4*>(lnb + t * 4);
    float4 o;
    o.x = fmaxf(0.f, (a4.x - mean) * rinv * g4.x + l4.x);
    o.y = fmaxf(0.f, (a4.y - mean) * rinv * g4.y + l4.y);
    o.z = fmaxf(0.f, (a4.z - mean) * rinv * g4.z + l4.z);
    o.w = fmaxf(0.f, (a4.w - mean) * rinv * g4.w + l4.w);
    *reinterpret_cast<float4*>(out + (size_t)v * HH + t * 4) = o;
  }
}

// ---------------- level-0 assignment ----------------
__global__ void __launch_bounds__(256) k_assign0(
    const float* __restrict__ bottom, const float* __restrict__ W,
    const float* __restrict__ bias, uint32_t kk0, uint32_t kk1)
{
  int warp = threadIdx.x >> 5, lane = threadIdx.x & 31;
  int v = blockIdx.x * 8 + warp;
  float acc[NK0];
#pragma unroll
  for (int c = 0; c < NK0; c++) acc[c] = 0.f;
  const float* br = bottom + (size_t)v * HH;
  for (int k = lane; k < HH; k += 32) {
    float bv = br[k];
#pragma unroll
    for (int c = 0; c < NK0; c++) acc[c] = fmaf(bv, W[k * NK0 + c], acc[c]);
  }
#pragma unroll
  for (int c = 0; c < NK0; c++) {
#pragma unroll
    for (int o = 16; o; o >>= 1) acc[c] += __shfl_xor_sync(0xffffffffu, acc[c], o);
  }
  if (lane == 0) {
    int best = 0; float bz = -1e30f;
#pragma unroll
    for (int c = 0; c < NK0; c++) {
      float z = acc[c] + bias[c] + gumbel_at(kk0, kk1, (uint32_t)(v * NK0 + c), (uint32_t)(NN * NK0 / 2));
      if (z > bz) { bz = z; best = c; }
    }
    g_a0[v] = best;
  }
}

// ---------------- pooled stats: xc0 + adj0 ----------------
__global__ void __launch_bounds__(256) k_poolstats(const int* __restrict__ ei) {
  __shared__ float acc[NK0 * HH];
  int t = threadIdx.x;
  if (blockIdx.x < NN / 64) {
#pragma unroll
    for (int r = 0; r < NK0; r++) acc[r * HH + t] = 0.f;
    __syncthreads();
    int v0 = blockIdx.x * 64;
    for (int n = 0; n < 64; n++) {
      int v = v0 + n;
      int c = g_a0[v];
      acc[c * HH + t] += g_bottom[(size_t)v * HH + t];
    }
    __syncthreads();
    for (int r = 0; r < NK0; r++) atomicAdd(&g_xc0[r * HH + t], acc[r * HH + t]);
  } else {
    if (t < NK0 * NK0) acc[t] = 0.f;
    __syncthreads();
    int base = (blockIdx.x - NN / 64) * 4096;
    for (int i = t; i < 4096; i += 256) {
      int e = base + i;
      int cs = g_a0[ei[e]], cd = g_a0[ei[EE + e]];
      atomicAdd(&acc[cs * NK0 + cd], 1.0f);
    }
    __syncthreads();
    if (t < NK0 * NK0) atomicAdd(&g_adj0[t], acc[t]);
  }
}

// ---------------- merged pooling: level0 + level1 + contrib (1 block) -------------
__global__ void __launch_bounds__(256) k_pool(
    const float* __restrict__ enc0W, const float* __restrict__ enc0b,
    const float* __restrict__ lin1W, const float* __restrict__ lin1b,
    const float* __restrict__ enc1W, const float* __restrict__ enc1b,
    const float* __restrict__ fc1W,
    uint32_t kk0, uint32_t kk1)
{
  int f = threadIdx.x;
  __shared__ float xcn0[NK0][HH];
  __shared__ float adjn[NK0 * NK0];
  __shared__ float msh[NK0][HH];
  __shared__ float red[8];
  __shared__ float lg[NK0 * NK1];
  __shared__ int a1s[NK0];
  __shared__ float xcn1[NK1][HH];
  __shared__ float adj1[NK1 * NK1];
  __shared__ float m1[NK1][HH];

  for (int r = 0; r < NK0; r++) {
    float x = g_xc0[r * HH + f];
    float ss = blockReduceSum256(x * x, red);
    float nrm = fmaxf(sqrtf(ss), 1e-12f);
    xcn0[r][f] = x / nrm;
  }
  float av = (f < NK0 * NK0) ? g_adj0[f] : 0.f;
  float sA = blockReduceSum256(av, red);
  if (f < NK0 * NK0) adjn[f] = av / sA;
  __syncthreads();
  for (int r = 0; r < NK0; r++) {
    float m = 0.f;
#pragma unroll
    for (int c = 0; c < NK0; c++) m = fmaf(adjn[r * NK0 + c], xcn0[c][f], m);
    msh[r][f] = m;
  }
  __syncthreads();
  {
    float acc[NK0];
#pragma unroll
    for (int r = 0; r < NK0; r++) acc[r] = 0.f;
    for (int k = 0; k < HH; k++) {
      float w = enc0W[(size_t)k * HH + f];
#pragma unroll
      for (int r = 0; r < NK0; r++) acc[r] = fmaf(msh[r][k], w, acc[r]);
    }
    float bb = enc0b[f];
#pragma unroll
    for (int r = 0; r < NK0; r++) g_lat1[r * HH + f] = tanhf(acc[r] + bb);
  }
  __syncthreads();

  if (f < NK0 * NK1) {
    int r = f / NK1, c = f % NK1;
    float acc = lin1b[c];
    for (int k = 0; k < HH; k++) acc = fmaf(g_lat1[r * HH + k], lin1W[k * NK1 + c], acc);
    lg[f] = acc;
  }
  if (f < NK1 * NK1) adj1[f] = 0.f;
  __syncthreads();
  if (f < NK0) {
    int best = 0; float bz = -1e30f;
#pragma unroll
    for (int c = 0; c < NK1; c++) {
      float z = lg[f * NK1 + c] + gumbel_at(kk0, kk1, (uint32_t)(f * NK1 + c), (uint32_t)(NK0 * NK1 / 2));
      if (z > bz) { bz = z; best = c; }
    }
    a1s[f] = best; g_a1[f] = best;
  }
  __syncthreads();
  for (int c = 0; c < NK1; c++) {
    float accv = 0.f;
    for (int r = 0; r < NK0; r++) if (a1s[r] == c) accv += g_lat1[r * HH + f];
    float ss = blockReduceSum256(accv * accv, red);
    float nrm = fmaxf(sqrtf(ss), 1e-12f);
    xcn1[c][f] = accv / nrm;
  }
  if (f < NK0 * NK0) {
    int r1 = f / NK0, r2 = f % NK0;
    atomicAdd(&adj1[a1s[r1] * NK1 + a1s[r2]], adjn[f]);
  }
  __syncthreads();
  float av1 = (f < NK1 * NK1) ? adj1[f] : 0.f;
  float s1 = blockReduceSum256(av1, red);
  if (f < NK1 * NK1) adj1[f] = av1 / s1;
  __syncthreads();
  for (int c = 0; c < NK1; c++) {
    float m = 0.f;
#pragma unroll
    for (int c2 = 0; c2 < NK1; c2++) m = fmaf(adj1[c * NK1 + c2], xcn1[c2][f], m);
    m1[c][f] = m;
  }
  __syncthreads();
  {
    float acc[NK1];
#pragma unroll
    for (int c = 0; c < NK1; c++) acc[c] = 0.f;
    for (int k = 0; k < HH; k++) {
      float w = enc1W[(size_t)k * HH + f];
#pragma unroll
      for (int c = 0; c < NK1; c++) acc[c] = fmaf(m1[c][k], w, acc[c]);
    }
    float bb = enc1b[f];
#pragma unroll
    for (int c = 0; c < NK1; c++) g_lat2[c * HH + f] = tanhf(acc[c] + bb);
  }
  __syncthreads();

  {
    int c1s[NK0];
#pragma unroll
    for (int c = 0; c < NK0; c++) c1s[c] = a1s[c];
    float acc[NK0];
#pragma unroll
    for (int c = 0; c < NK0; c++) acc[c] = 0.f;
    for (int k = 0; k < HH; k++) {
      float w1 = fc1W[(size_t)(HH + k) * HH + f];
      float w2 = fc1W[(size_t)(2 * HH + k) * HH + f];
#pragma unroll
      for (int c = 0; c < NK0; c++) {
        acc[c] = fmaf(g_lat1[c * HH + k], w1, acc[c]);
        acc[c] = fmaf(g_lat2[c1s[c] * HH + k], w2, acc[c]);
      }
    }
#pragma unroll
    for (int c = 0; c < NK0; c++) g_contrib[c * HH + f] = acc[c];
  }
}

// ---------------- final: relu(t0 + contrib[a0]) @ fc2 + log_softmax ----------------
__global__ void __launch_bounds__(256) k_final(
    const float* __restrict__ hidden, const float* __restrict__ W,
    const float* __restrict__ bias, float* __restrict__ out)
{
  int warp = threadIdx.x >> 5, lane = threadIdx.x & 31;
  int v = blockIdx.x * 8 + warp;
  int j = lane & 15, h = lane >> 4;
  const float* hr = hidden + (size_t)v * HH + h * 128;
  const float* cr = g_contrib + (size_t)g_a0[v] * HH + h * 128;
  const float* Wp = W + (size_t)h * 128 * NOUTC + j;
  float acc = 0.f;
#pragma unroll 4
  for (int q = 0; q < 32; q++) {
    float4 hv4 = *reinterpret_cast<const float4*>(hr + q * 4);
    float4 cv4 = *reinterpret_cast<const float4*>(cr + q * 4);
    float v0 = fmaxf(hv4.x + cv4.x, 0.f);
    float v1 = fmaxf(hv4.y + cv4.y, 0.f);
    float v2 = fmaxf(hv4.z + cv4.z, 0.f);
    float v3 = fmaxf(hv4.w + cv4.w, 0.f);
    acc = fmaf(v0, Wp[(q * 4 + 0) * NOUTC], acc);
    acc = fmaf(v1, Wp[(q * 4 + 1) * NOUTC], acc);
    acc = fmaf(v2, Wp[(q * 4 + 2) * NOUTC], acc);
    acc = fmaf(v3, Wp[(q * 4 + 3) * NOUTC], acc);
  }
  acc += __shfl_xor_sync(0xffffffffu, acc, 16);
  acc += bias[j];
  float mx = acc;
#pragma unroll
  for (int o = 8; o; o >>= 1) mx = fmaxf(mx, __shfl_xor_sync(0xffffffffu, mx, o));
  float e = expf(acc - mx);
  float se = e;
#pragma unroll
  for (int o = 8; o; o >>= 1) se += __shfl_xor_sync(0xffffffffu, se, o);
  if (lane < 16) out[(size_t)v * NOUTC + j] = acc - mx - logf(se);
}

// ---------------- stream/event resources (created once; identical work per call) --
struct SideStream {
  cudaStream_t s2;
  cudaEvent_t e1, e2, e3, e4, e5, e6;
  SideStream() {
    cudaStreamCreateWithFlags(&s2, cudaStreamNonBlocking);
    cudaEventCreateWithFlags(&e1, cudaEventDisableTiming);
    cudaEventCreateWithFlags(&e2, cudaEventDisableTiming);
    cudaEventCreateWithFlags(&e3, cudaEventDisableTiming);
    cudaEventCreateWithFlags(&e4, cudaEventDisableTiming);
    cudaEventCreateWithFlags(&e5, cudaEventDisableTiming);
    cudaEventCreateWithFlags(&e6, cudaEventDisableTiming);
  }
};

// ---------------- launcher ----------------
extern "C" void kernel_launch(void* const* d_in, const int* in_sizes, int n_in,
                              void* d_out, int out_size) {
  const float* x       = (const float*)d_in[0];
  const int*   ei      = (const int*)  d_in[1];
  const float* ew      = (const float*)d_in[2];
  const float* conv1_W = (const float*)d_in[3];
  const float* conv1_b = (const float*)d_in[4];
  const float* conv2_W = (const float*)d_in[5];
  const float* conv2_b = (const float*)d_in[6];
  const float* ln1_g   = (const float*)d_in[7];
  const float* ln1_b   = (const float*)d_in[8];
  const float* ln2_g   = (const float*)d_in[9];
  const float* ln2_b   = (const float*)d_in[10];
  const float* efc1_W  = (const float*)d_in[11];
  const float* efc1_b  = (const float*)d_in[12];
  const float* efc2_W  = (const float*)d_in[13];
  const float* efc2_b  = (const float*)d_in[14];
  const float* lin0_W  = (const float*)d_in[15];
  const float* lin0_b  = (const float*)d_in[16];
  const float* lin1_W  = (const float*)d_in[17];
  const float* lin1_b  = (const float*)d_in[18];
  const float* enc0_W  = (const float*)d_in[19];
  const float* enc0_b  = (const float*)d_in[20];
  const float* enc1_W  = (const float*)d_in[21];
  const float* enc1_b  = (const float*)d_in[22];
  const float* fc1_W   = (const float*)d_in[23];
  const float* fc1_b   = (const float*)d_in[24];
  const float* fc2_W   = (const float*)d_in[25];
  const float* fc2_b   = (const float*)d_in[26];
  float* out = (float*)d_out;

  float *p_t0, *p_t1, *p_h1, *p_h2, *p_bottom;
  cudaGetSymbolAddress((void**)&p_t0, g_t0);
  cudaGetSymbolAddress((void**)&p_t1, g_t1);
  cudaGetSymbolAddress((void**)&p_h1, g_h1);
  cudaGetSymbolAddress((void**)&p_h2, g_h2);
  cudaGetSymbolAddress((void**)&p_bottom, g_bottom);

  cudaFuncSetAttribute(k_tf32gemm, cudaFuncAttributeMaxDynamicSharedMemorySize, GEMM_SMEM);

  static SideStream S;

  uint32_t kA0, kA1, kB0, kB1;
  tf2x32(0u, 42u, 0u, 0u, kA0, kA1);
  tf2x32(0u, 42u, 0u, 1u, kB0, kB1);

  dim3 g2(2, 125);

  // fork: preprocessing on side stream, concurrent with GEMM-1 on main
  cudaEventRecord(S.e1, 0);
  cudaStreamWaitEvent(S.s2, S.e1, 0);
  k_prep<<<63, 256, 0, S.s2>>>();
  k_hist<<<EE / 256, 256, 0, S.s2>>>(ei, ew);
  k_scan_dinv<<<1, 256, 0, S.s2>>>();
  // main: GCN-1 dense (4th submission — profiled)
  k_tf32gemm<<<g2, 256, GEMM_SMEM>>>(x, nullptr, nullptr, FF, 0, 0, FF, 0, 0,
                                     conv1_W, HH, p_t0, HH, 0, 0, nullptr);
  k_scatter<<<EE / 256, 256, 0, S.s2>>>(ei, ew);
  cudaEventRecord(S.e2, S.s2);

  // join before SpMM-1
  cudaStreamWaitEvent(0, S.e2, 0);
  k_spmm_ln_relu<<<NN, 256>>>(p_t0, p_h1, conv1_b, ln1_g, ln1_b);
  cudaEventRecord(S.e5, 0);

  // side: efc1 partial (x + h1 segments, K=456) overlaps GEMM2+SpMM2 on main
  cudaStreamWaitEvent(S.s2, S.e5, 0);
  k_tf32gemm<<<g2, 256, GEMM_SMEM, S.s2>>>(x, p_h1, nullptr, FF, HH, 0, FF, HH, 0,
                                           efc1_W, HH, p_t1, HH, 0, 0, nullptr);
  cudaEventRecord(S.e6, S.s2);

  // main: GCN layer 2
  k_tf32gemm<<<g2, 256, GEMM_SMEM>>>(p_h1, nullptr, nullptr, HH, 0, 0, HH, 0, 0,
                                     conv2_W, HH, p_t0, HH, 0, 0, nullptr);
  k_spmm_ln_relu<<<NN, 256>>>(p_t0, p_h2, conv2_b, ln2_g, ln2_b);

  // main: efc1 h2-segment accumulates onto partial, +bias+relu; then efc2
  cudaStreamWaitEvent(0, S.e6, 0);
  k_tf32gemm<<<g2, 256, GEMM_SMEM>>>(p_h2, nullptr, nullptr, HH, 0, 0, HH, 0, 0,
                                     efc1_W + (size_t)(FF + HH) * HH, HH, p_t1, HH, 2, 1, efc1_b);
  k_tf32gemm<<<g2, 256, GEMM_SMEM>>>(p_t1, nullptr, nullptr, HH, 0, 0, HH, 0, 0,
                                     efc2_W, HH, p_bottom, HH, 1, 0, efc2_b);
  cudaEventRecord(S.e3, 0);

  // pooling chain on side stream, concurrent with fc1 GEMM on main
  cudaStreamWaitEvent(S.s2, S.e3, 0);
  k_assign0<<<NN / 8, 256, 0, S.s2>>>(p_bottom, lin0_W, lin0_b, kA0, kA1);
  k_poolstats<<<NN / 64 + EE / 4096, 256, 0, S.s2>>>(ei);
  k_pool<<<1, 256, 0, S.s2>>>(enc0_W, enc0_b, lin1_W, lin1_b, enc1_W, enc1_b, fc1_W, kB0, kB1);
  cudaEventRecord(S.e4, S.s2);

  // fc1 mainloop (bias only; contrib folded into k_final)
  k_tf32gemm<<<g2, 256, GEMM_SMEM>>>(p_bottom, nullptr, nullptr, HH, 0, 0, HH, 0, 0,
                                     fc1_W, HH, p_t0, HH, 1, 0, fc1_b);
  cudaStreamWaitEvent(0, S.e4, 0);
  k_final<<<NN / 8, 256>>>(p_t0, fc2_W, fc2_b, out);
}

// round 15
// speedup vs baseline: 1.0735x; 1.0735x over previous
#include <cuda_runtime.h>
#include <cstdint>
#include <cmath>

#define NN   16000
#define EE   512000
#define FF   200
#define HH   256
#define NK0  10
#define NK1  5
#define NOUTC 16

// ---------------- device scratch (no allocations allowed) ----------------
__device__ float g_t0[NN*HH];
__device__ float g_h1[NN*HH];
__device__ float g_h2[NN*HH];
__device__ float g_bottom[NN*HH];
__device__ int   g_srcs[EE];
__device__ float g_wn[EE];
__device__ int   g_rowptr[NN+1];
__device__ int   g_cnt[NN];
__device__ int   g_fill[NN];
__device__ float g_degw[NN];
__device__ float g_dinv[NN];
__device__ float g_selfn[NN];
__device__ int   g_a0[NN];
__device__ float g_xc0[NK0*HH];
__device__ float g_adj0[NK0*NK0];
__device__ float g_lat1[NK0*HH];
__device__ int   g_a1[NK0];
__device__ float g_lat2[NK1*HH];
__device__ float g_contrib[NK0*HH];

// ---------------- threefry2x32 (exact JAX semantics) ----------------
__host__ __device__ inline void tf2x32(uint32_t k0, uint32_t k1, uint32_t x0, uint32_t x1,
                                       uint32_t& o0, uint32_t& o1) {
  uint32_t ks2 = k0 ^ k1 ^ 0x1BD11BDAu;
#define ROTL32(x,d) (((x)<<(d))|((x)>>(32-(d))))
#define TFRND(r) { x0 += x1; x1 = ROTL32(x1,(r)); x1 ^= x0; }
  x0 += k0; x1 += k1;
  TFRND(13) TFRND(15) TFRND(26) TFRND(6)   x0 += k1;  x1 += ks2 + 1u;
  TFRND(17) TFRND(29) TFRND(16) TFRND(24)  x0 += ks2; x1 += k0 + 2u;
  TFRND(13) TFRND(15) TFRND(26) TFRND(6)   x0 += k0;  x1 += k1 + 3u;
  TFRND(17) TFRND(29) TFRND(16) TFRND(24)  x0 += k1;  x1 += ks2 + 4u;
  TFRND(13) TFRND(15) TFRND(26) TFRND(6)   x0 += ks2; x1 += k0 + 5u;
  o0 = x0; o1 = x1;
#undef TFRND
#undef ROTL32
}

__device__ __forceinline__ float gumbel_at(uint32_t k0, uint32_t k1, uint32_t t, uint32_t half) {
  uint32_t a, b, bits;
  if (t < half) { tf2x32(k0, k1, t, t + half, a, b); bits = a; }
  else          { tf2x32(k0, k1, t - half, t, a, b); bits = b; }
  float u01 = __uint_as_float((bits >> 9) | 0x3f800000u) - 1.0f;
  float u = fmaxf(1e-10f, u01 * (1.0f - 1e-10f) + 1e-10f);
  return -logf(-logf(u));
}

// ---------------- helpers ----------------
__device__ __forceinline__ float blockReduceSum256(float v, float* red) {
#pragma unroll
  for (int o = 16; o; o >>= 1) v += __shfl_xor_sync(0xffffffffu, v, o);
  int w = threadIdx.x >> 5;
  if ((threadIdx.x & 31) == 0) red[w] = v;
  __syncthreads();
  float r;
  if (threadIdx.x < 8) {
    r = red[threadIdx.x];
#pragma unroll
    for (int o = 4; o; o >>= 1) r += __shfl_xor_sync(0xffu, r, o);
    if (threadIdx.x == 0) red[0] = r;
  }
  __syncthreads();
  r = red[0];
  __syncthreads();
  return r;
}

__device__ __forceinline__ void mma_tf32(float c[4], const uint32_t a[4], const uint32_t b[2]) {
  asm volatile(
      "mma.sync.aligned.m16n8k8.row.col.f32.tf32.tf32.f32 "
      "{%0,%1,%2,%3}, {%4,%5,%6,%7}, {%8,%9}, {%0,%1,%2,%3};"
      : "+f"(c[0]), "+f"(c[1]), "+f"(c[2]), "+f"(c[3])
      : "r"(a[0]), "r"(a[1]), "r"(a[2]), "r"(a[3]), "r"(b[0]), "r"(b[1]));
}

__device__ __forceinline__ void cpasync16(uint32_t dst, const void* src, int src_bytes) {
  asm volatile("cp.async.cg.shared.global [%0], [%1], 16, %2;"
               :: "r"(dst), "l"(src), "r"(src_bytes));
}
__device__ __forceinline__ void cpasync_commit() {
  asm volatile("cp.async.commit_group;");
}
template <int N>
__device__ __forceinline__ void cpasync_wait() {
  asm volatile("cp.async.wait_group %0;" :: "n"(N));
}

// ---------------- graph preprocessing (split kernels, side stream) ----------------
__global__ void k_prep() {
  int i = blockIdx.x * blockDim.x + threadIdx.x;
  if (i < NN) { g_cnt[i] = 0; g_fill[i] = 0; g_degw[i] = 0.f; }
  if (i < NK0*HH) g_xc0[i] = 0.f;
  if (i < NK0*NK0) g_adj0[i] = 0.f;
}

__global__ void k_hist(const int* __restrict__ ei, const float* __restrict__ ew) {
  int e = blockIdx.x * blockDim.x + threadIdx.x;
  if (e >= EE) return;
  int d = ei[EE + e];
  atomicAdd(&g_cnt[d], 1);
  atomicAdd(&g_degw[d], ew[e]);
}

// 1024-thread two-level shfl scan (CH=16) + dinv
__global__ void k_scan_dinv() {
  __shared__ int warp_tot[32];
  int t = threadIdx.x;
  const int CH = 16;
  int s0 = t * CH;
  int s1 = s0 + CH; if (s1 > NN) s1 = NN;
  int s = 0;
  for (int i = s0; i < s1; i++) s += g_cnt[i];
  int lane = t & 31, wid = t >> 5;
  // inclusive warp scan
  int v = s;
#pragma unroll
  for (int o = 1; o < 32; o <<= 1) {
    int n = __shfl_up_sync(0xffffffffu, v, o);
    if (lane >= o) v += n;
  }
  if (lane == 31) warp_tot[wid] = v;
  __syncthreads();
  if (wid == 0) {
    int w = warp_tot[lane];
#pragma unroll
    for (int o = 1; o < 32; o <<= 1) {
      int n = __shfl_up_sync(0xffffffffu, w, o);
      if (lane >= o) w += n;
    }
    warp_tot[lane] = w;
  }
  __syncthreads();
  int excl = v - s + (wid > 0 ? warp_tot[wid - 1] : 0);
  int run = excl;
  for (int i = s0; i < s1; i++) { g_rowptr[i] = run; run += g_cnt[i]; }
  if (s0 < NN && s1 == NN) g_rowptr[NN] = run;
  for (int i = t; i < NN; i += 1024) {
    float deg = g_degw[i] + 1.0f;
    float di = rsqrtf(deg);
    g_dinv[i] = di;
    g_selfn[i] = di * di;
  }
}

__global__ void k_scatter(const int* __restrict__ ei, const float* __restrict__ ew) {
  int e = blockIdx.x * blockDim.x + threadIdx.x;
  if (e >= EE) return;
  int s = ei[e], d = ei[EE + e];
  int pos = g_rowptr[d] + atomicAdd(&g_fill[d], 1);
  g_srcs[pos] = s;
  g_wn[pos] = ew[e] * g_dinv[s] * g_dinv[d];
}

// ---------------- tf32 tensor-core GEMM (BK=32, 3-stage cp.async pipeline) --------
#define A_WORDS     4608
#define STAGE_WORDS 8832
#define GEMM_SMEM   (3 * STAGE_WORDS * 4)
__global__ void __launch_bounds__(256, 2) k_tf32gemm(
    const float* __restrict__ A0, const float* __restrict__ A1, const float* __restrict__ A2,
    int K0s, int K1s, int K2s, int lda0, int lda1, int lda2,
    const float* __restrict__ B, int ldb, float* __restrict__ C, int ldc,
    int epi, const float* __restrict__ bias)
{
  extern __shared__ uint32_t smem[];
  const int tid = threadIdx.x;
  const int lane = tid & 31, wid = tid >> 5;
  const int warpM = (wid >> 2) * 64, warpN = (wid & 3) * 32;
  const int bm = blockIdx.y * 128, bn = blockIdx.x * 128;

  const float* Aseg[3] = {A0, A1, A2};
  const int    Kseg[3] = {K0s, K1s, K2s};
  const int    Lseg[3] = {lda0, lda1, lda2};
  const int    Boff[3] = {0, K0s, K0s + K1s};

  float c[4][4][4];
#pragma unroll
  for (int mi = 0; mi < 4; mi++)
#pragma unroll
    for (int ni = 0; ni < 4; ni++)
#pragma unroll
      for (int q = 0; q < 4; q++) c[mi][ni][q] = 0.f;

  const int kc    = (tid & 7) * 4;
  const int arow0 = tid >> 3;
  const int bkrow = tid >> 5;
  const int bcol  = (tid & 31) * 4;
  const uint32_t sbase = (uint32_t)__cvta_generic_to_shared(smem);

  int T = 0;
#pragma unroll
  for (int s = 0; s < 3; s++) if (Kseg[s] > 0) T += (Kseg[s] + 31) / 32;

  int is = 0, ik = 0;
  auto issue_next = [&](int st) {
    const float* A = Aseg[is];
    const int lda = Lseg[is];
    const float* Bp = B + (size_t)Boff[is] * ldb;
    const int Krem = Kseg[is] - ik;
    uint32_t abase = sbase + (st * STAGE_WORDS) * 4;
    uint32_t bbase = sbase + (st * STAGE_WORDS + A_WORDS) * 4;
    int szA = (kc < Krem) ? 16 : 0;
#pragma unroll
    for (int u = 0; u < 4; u++) {
      int row = arow0 + u * 32;
      const float* src = szA ? (A + (size_t)(bm + row) * lda + ik + kc) : A;
      cpasync16(abase + (row * 36 + kc) * 4, src, szA);
    }
#pragma unroll
    for (int u = 0; u < 4; u++) {
      int krow = bkrow + u * 8;
      int szB = (krow < Krem) ? 16 : 0;
      const float* src = szB ? (Bp + (size_t)(ik + krow) * ldb + bn + bcol) : Bp;
      cpasync16(bbase + (krow * 132 + bcol) * 4, src, szB);
    }
    ik += 32;
    if (ik >= Kseg[is]) { is++; ik = 0; while (is < 3 && Kseg[is] == 0) is++; }
  };

  auto compute = [&](int st) {
    const uint32_t* Asb = smem + st * STAGE_WORDS;
    const uint32_t* Bsb = smem + st * STAGE_WORDS + A_WORDS;
#pragma unroll
    for (int kk = 0; kk < 4; kk++) {
      const int ks = kk * 8 + (lane & 3);
      const int rg = lane >> 2;
      uint32_t af[4][4];
#pragma unroll
      for (int mi = 0; mi < 4; mi++) {
        int row = warpM + mi * 16 + rg;
        af[mi][0] = Asb[row * 36 + ks];
        af[mi][1] = Asb[(row + 8) * 36 + ks];
        af[mi][2] = Asb[row * 36 + ks + 4];
        af[mi][3] = Asb[(row + 8) * 36 + ks + 4];
      }
      uint32_t bf[4][2];
#pragma unroll
      for (int ni = 0; ni < 4; ni++) {
        int col = warpN + ni * 8 + rg;
        bf[ni][0] = Bsb[ks * 132 + col];
        bf[ni][1] = Bsb[(ks + 4) * 132 + col];
      }
#pragma unroll
      for (int mi = 0; mi < 4; mi++)
#pragma unroll
        for (int ni = 0; ni < 4; ni++) mma_tf32(c[mi][ni], af[mi], bf[ni]);
    }
  };

  issue_next(0);
  cpasync_commit();
  if (T > 1) issue_next(1);
  cpasync_commit();
  for (int i = 0; i < T; i++) {
    if (i + 1 < T) cpasync_wait<1>(); else cpasync_wait<0>();
    __syncthreads();
    compute(i % 3);
    if (i + 2 < T) { issue_next((i + 2) % 3); cpasync_commit(); }
  }

  const int rg = lane >> 2, cg2 = (lane & 3) * 2;
#pragma unroll
  for (int mi = 0; mi < 4; mi++) {
    int raI = bm + warpM + mi * 16 + rg;
    int rbI = raI + 8;
#pragma unroll
    for (int ni = 0; ni < 4; ni++) {
      int cb = bn + warpN + ni * 8 + cg2;
      float v0 = c[mi][ni][0], v1 = c[mi][ni][1];
      float v2 = c[mi][ni][2], v3 = c[mi][ni][3];
      if (epi >= 1) { float b0 = bias[cb], b1 = bias[cb + 1]; v0 += b0; v1 += b1; v2 += b0; v3 += b1; }
      if (epi >= 2) { v0 = fmaxf(v0, 0.f); v1 = fmaxf(v1, 0.f); v2 = fmaxf(v2, 0.f); v3 = fmaxf(v3, 0.f); }
      *reinterpret_cast<float2*>(C + (size_t)raI * ldc + cb) = make_float2(v0, v1);
      *reinterpret_cast<float2*>(C + (size_t)rbI * ldc + cb) = make_float2(v2, v3);
    }
  }
}

// ---------------- SpMM + self loop + bias + LayerNorm + ReLU (256 thr, 4 slices) --
__global__ void __launch_bounds__(256) k_spmm_ln_relu(
    const float* __restrict__ hin, float* __restrict__ out,
    const float* __restrict__ bias, const float* __restrict__ lng,
    const float* __restrict__ lnb)
{
  __shared__ float4 part[4][64];
  __shared__ float red[8];
  int v = blockIdx.x;
  int t = threadIdx.x;
  int fg = t & 63, es = t >> 6;
  int p0 = g_rowptr[v], p1 = g_rowptr[v + 1];
  float4 acc = make_float4(0.f, 0.f, 0.f, 0.f);
  if (es == 0) {
    float sn = g_selfn[v];
    float4 hv = *reinterpret_cast<const float4*>(hin + (size_t)v * HH + fg * 4);
    acc.x = hv.x * sn; acc.y = hv.y * sn; acc.z = hv.z * sn; acc.w = hv.w * sn;
  }
#pragma unroll 4
  for (int p = p0 + es; p < p1; p += 4) {
    int srow = g_srcs[p];
    float w = g_wn[p];
    float4 hv = *reinterpret_cast<const float4*>(hin + (size_t)srow * HH + fg * 4);
    acc.x = fmaf(hv.x, w, acc.x);
    acc.y = fmaf(hv.y, w, acc.y);
    acc.z = fmaf(hv.z, w, acc.z);
    acc.w = fmaf(hv.w, w, acc.w);
  }
  part[es][fg] = acc;
  __syncthreads();
  float4 a4 = make_float4(0.f, 0.f, 0.f, 0.f);
  float s = 0.f, sq = 0.f;
  if (t < 64) {
    float4 q0 = part[0][t], q1 = part[1][t], q2 = part[2][t], q3 = part[3][t];
    float4 b4 = *reinterpret_cast<const float4*>(bias + t * 4);
    a4.x = q0.x + q1.x + q2.x + q3.x + b4.x;
    a4.y = q0.y + q1.y + q2.y + q3.y + b4.y;
    a4.z = q0.z + q1.z + q2.z + q3.z + b4.z;
    a4.w = q0.w + q1.w + q2.w + q3.w + b4.w;
    s = a4.x + a4.y + a4.z + a4.w;
    sq = a4.x * a4.x + a4.y * a4.y + a4.z * a4.z + a4.w * a4.w;
  }
  float sum = blockReduceSum256(s, red);
  float sumsq = blockReduceSum256(sq, red);
  if (t < 64) {
    float mean = sum * (1.0f / HH);
    float var = sumsq * (1.0f / HH) - mean * mean;
    float rinv = rsqrtf(var + 1e-5f);
    float4 g4 = *reinterpret_cast<const float4*>(lng + t * 4);
    float4 l4 = *reinterpret_cast<const float4*>(lnb + t * 4);
    float4 o;
    o.x = fmaxf(0.f, (a4.x - mean) * rinv * g4.x + l4.x);
    o.y = fmaxf(0.f, (a4.y - mean) * rinv * g4.y + l4.y);
    o.z = fmaxf(0.f, (a4.z - mean) * rinv * g4.z + l4.z);
    o.w = fmaxf(0.f, (a4.w - mean) * rinv * g4.w + l4.w);
    *reinterpret_cast<float4*>(out + (size_t)v * HH + t * 4) = o;
  }
}

// ---------------- level-0 assignment ----------------
__global__ void __launch_bounds__(256) k_assign0(
    const float* __restrict__ bottom, const float* __restrict__ W,
    const float* __restrict__ bias, uint32_t kk0, uint32_t kk1)
{
  int warp = threadIdx.x >> 5, lane = threadIdx.x & 31;
  int v = blockIdx.x * 8 + warp;
  float acc[NK0];
#pragma unroll
  for (int c = 0; c < NK0; c++) acc[c] = 0.f;
  const float* br = bottom + (size_t)v * HH;
  for (int k = lane; k < HH; k += 32) {
    float bv = br[k];
#pragma unroll
    for (int c = 0; c < NK0; c++) acc[c] = fmaf(bv, W[k * NK0 + c], acc[c]);
  }
#pragma unroll
  for (int c = 0; c < NK0; c++) {
#pragma unroll
    for (int o = 16; o; o >>= 1) acc[c] += __shfl_xor_sync(0xffffffffu, acc[c], o);
  }
  if (lane == 0) {
    int best = 0; float bz = -1e30f;
#pragma unroll
    for (int c = 0; c < NK0; c++) {
      float z = acc[c] + bias[c] + gumbel_at(kk0, kk1, (uint32_t)(v * NK0 + c), (uint32_t)(NN * NK0 / 2));
      if (z > bz) { bz = z; best = c; }
    }
    g_a0[v] = best;
  }
}

// ---------------- pooled stats: xc0 + adj0 ----------------
__global__ void __launch_bounds__(256) k_poolstats(const int* __restrict__ ei) {
  __shared__ float acc[NK0 * HH];
  int t = threadIdx.x;
  if (blockIdx.x < NN / 64) {
#pragma unroll
    for (int r = 0; r < NK0; r++) acc[r * HH + t] = 0.f;
    __syncthreads();
    int v0 = blockIdx.x * 64;
    for (int n = 0; n < 64; n++) {
      int v = v0 + n;
      int c = g_a0[v];
      acc[c * HH + t] += g_bottom[(size_t)v * HH + t];
    }
    __syncthreads();
    for (int r = 0; r < NK0; r++) atomicAdd(&g_xc0[r * HH + t], acc[r * HH + t]);
  } else {
    if (t < NK0 * NK0) acc[t] = 0.f;
    __syncthreads();
    int base = (blockIdx.x - NN / 64) * 4096;
    for (int i = t; i < 4096; i += 256) {
      int e = base + i;
      int cs = g_a0[ei[e]], cd = g_a0[ei[EE + e]];
      atomicAdd(&acc[cs * NK0 + cd], 1.0f);
    }
    __syncthreads();
    if (t < NK0 * NK0) atomicAdd(&g_adj0[t], acc[t]);
  }
}

// ---------------- merged pooling: level0 + level1 + contrib (1 block) -------------
__global__ void __launch_bounds__(256) k_pool(
    const float* __restrict__ enc0W, const float* __restrict__ enc0b,
    const float* __restrict__ lin1W, const float* __restrict__ lin1b,
    const float* __restrict__ enc1W, const float* __restrict__ enc1b,
    const float* __restrict__ fc1W,
    uint32_t kk0, uint32_t kk1)
{
  int f = threadIdx.x;
  __shared__ float xcn0[NK0][HH];
  __shared__ float adjn[NK0 * NK0];
  __shared__ float msh[NK0][HH];
  __shared__ float red[8];
  __shared__ float lg[NK0 * NK1];
  __shared__ int a1s[NK0];
  __shared__ float xcn1[NK1][HH];
  __shared__ float adj1[NK1 * NK1];
  __shared__ float m1[NK1][HH];

  for (int r = 0; r < NK0; r++) {
    float x = g_xc0[r * HH + f];
    float ss = blockReduceSum256(x * x, red);
    float nrm = fmaxf(sqrtf(ss), 1e-12f);
    xcn0[r][f] = x / nrm;
  }
  float av = (f < NK0 * NK0) ? g_adj0[f] : 0.f;
  float sA = blockReduceSum256(av, red);
  if (f < NK0 * NK0) adjn[f] = av / sA;
  __syncthreads();
  for (int r = 0; r < NK0; r++) {
    float m = 0.f;
#pragma unroll
    for (int c = 0; c < NK0; c++) m = fmaf(adjn[r * NK0 + c], xcn0[c][f], m);
    msh[r][f] = m;
  }
  __syncthreads();
  {
    float acc[NK0];
#pragma unroll
    for (int r = 0; r < NK0; r++) acc[r] = 0.f;
    for (int k = 0; k < HH; k++) {
      float w = enc0W[(size_t)k * HH + f];
#pragma unroll
      for (int r = 0; r < NK0; r++) acc[r] = fmaf(msh[r][k], w, acc[r]);
    }
    float bb = enc0b[f];
#pragma unroll
    for (int r = 0; r < NK0; r++) g_lat1[r * HH + f] = tanhf(acc[r] + bb);
  }
  __syncthreads();

  if (f < NK0 * NK1) {
    int r = f / NK1, c = f % NK1;
    float acc = lin1b[c];
    for (int k = 0; k < HH; k++) acc = fmaf(g_lat1[r * HH + k], lin1W[k * NK1 + c], acc);
    lg[f] = acc;
  }
  if (f < NK1 * NK1) adj1[f] = 0.f;
  __syncthreads();
  if (f < NK0) {
    int best = 0; float bz = -1e30f;
#pragma unroll
    for (int c = 0; c < NK1; c++) {
      float z = lg[f * NK1 + c] + gumbel_at(kk0, kk1, (uint32_t)(f * NK1 + c), (uint32_t)(NK0 * NK1 / 2));
      if (z > bz) { bz = z; best = c; }
    }
    a1s[f] = best; g_a1[f] = best;
  }
  __syncthreads();
  for (int c = 0; c < NK1; c++) {
    float accv = 0.f;
    for (int r = 0; r < NK0; r++) if (a1s[r] == c) accv += g_lat1[r * HH + f];
    float ss = blockReduceSum256(accv * accv, red);
    float nrm = fmaxf(sqrtf(ss), 1e-12f);
    xcn1[c][f] = accv / nrm;
  }
  if (f < NK0 * NK0) {
    int r1 = f / NK0, r2 = f % NK0;
    atomicAdd(&adj1[a1s[r1] * NK1 + a1s[r2]], adjn[f]);
  }
  __syncthreads();
  float av1 = (f < NK1 * NK1) ? adj1[f] : 0.f;
  float s1 = blockReduceSum256(av1, red);
  if (f < NK1 * NK1) adj1[f] = av1 / s1;
  __syncthreads();
  for (int c = 0; c < NK1; c++) {
    float m = 0.f;
#pragma unroll
    for (int c2 = 0; c2 < NK1; c2++) m = fmaf(adj1[c * NK1 + c2], xcn1[c2][f], m);
    m1[c][f] = m;
  }
  __syncthreads();
  {
    float acc[NK1];
#pragma unroll
    for (int c = 0; c < NK1; c++) acc[c] = 0.f;
    for (int k = 0; k < HH; k++) {
      float w = enc1W[(size_t)k * HH + f];
#pragma unroll
      for (int c = 0; c < NK1; c++) acc[c] = fmaf(m1[c][k], w, acc[c]);
    }
    float bb = enc1b[f];
#pragma unroll
    for (int c = 0; c < NK1; c++) g_lat2[c * HH + f] = tanhf(acc[c] + bb);
  }
  __syncthreads();

  {
    int c1s[NK0];
#pragma unroll
    for (int c = 0; c < NK0; c++) c1s[c] = a1s[c];
    float acc[NK0];
#pragma unroll
    for (int c = 0; c < NK0; c++) acc[c] = 0.f;
    for (int k = 0; k < HH; k++) {
      float w1 = fc1W[(size_t)(HH + k) * HH + f];
      float w2 = fc1W[(size_t)(2 * HH + k) * HH + f];
#pragma unroll
      for (int c = 0; c < NK0; c++) {
        acc[c] = fmaf(g_lat1[c * HH + k], w1, acc[c]);
        acc[c] = fmaf(g_lat2[c1s[c] * HH + k], w2, acc[c]);
      }
    }
#pragma unroll
    for (int c = 0; c < NK0; c++) g_contrib[c * HH + f] = acc[c];
  }
}

// ---------------- final: relu(t0 + contrib[a0]) @ fc2 + log_softmax ----------------
__global__ void __launch_bounds__(256) k_final(
    const float* __restrict__ hidden, const float* __restrict__ W,
    const float* __restrict__ bias, float* __restrict__ out)
{
  int warp = threadIdx.x >> 5, lane = threadIdx.x & 31;
  int v = blockIdx.x * 8 + warp;
  int j = lane & 15, h = lane >> 4;
  const float* hr = hidden + (size_t)v * HH;
  const float* cr = g_contrib + (size_t)g_a0[v] * HH;
  float acc = 0.f;
  for (int k = h; k < HH; k += 2) {
    float hv = fmaxf(hr[k] + cr[k], 0.f);
    acc = fmaf(hv, W[k * NOUTC + j], acc);
  }
  acc += __shfl_xor_sync(0xffffffffu, acc, 16);
  acc += bias[j];
  float mx = acc;
#pragma unroll
  for (int o = 8; o; o >>= 1) mx = fmaxf(mx, __shfl_xor_sync(0xffffffffu, mx, o));
  float e = expf(acc - mx);
  float se = e;
#pragma unroll
  for (int o = 8; o; o >>= 1) se += __shfl_xor_sync(0xffffffffu, se, o);
  if (lane < 16) out[(size_t)v * NOUTC + j] = acc - mx - logf(se);
}

// ---------------- stream/event resources (created once; identical work per call) --
struct SideStream {
  cudaStream_t s2;
  cudaEvent_t e1, e2, e3, e4;
  SideStream() {
    cudaStreamCreateWithFlags(&s2, cudaStreamNonBlocking);
    cudaEventCreateWithFlags(&e1, cudaEventDisableTiming);
    cudaEventCreateWithFlags(&e2, cudaEventDisableTiming);
    cudaEventCreateWithFlags(&e3, cudaEventDisableTiming);
    cudaEventCreateWithFlags(&e4, cudaEventDisableTiming);
  }
};

// ---------------- launcher ----------------
extern "C" void kernel_launch(void* const* d_in, const int* in_sizes, int n_in,
                              void* d_out, int out_size) {
  const float* x       = (const float*)d_in[0];
  const int*   ei      = (const int*)  d_in[1];
  const float* ew      = (const float*)d_in[2];
  const float* conv1_W = (const float*)d_in[3];
  const float* conv1_b = (const float*)d_in[4];
  const float* conv2_W = (const float*)d_in[5];
  const float* conv2_b = (const float*)d_in[6];
  const float* ln1_g   = (const float*)d_in[7];
  const float* ln1_b   = (const float*)d_in[8];
  const float* ln2_g   = (const float*)d_in[9];
  const float* ln2_b   = (const float*)d_in[10];
  const float* efc1_W  = (const float*)d_in[11];
  const float* efc1_b  = (const float*)d_in[12];
  const float* efc2_W  = (const float*)d_in[13];
  const float* efc2_b  = (const float*)d_in[14];
  const float* lin0_W  = (const float*)d_in[15];
  const float* lin0_b  = (const float*)d_in[16];
  const float* lin1_W  = (const float*)d_in[17];
  const float* lin1_b  = (const float*)d_in[18];
  const float* enc0_W  = (const float*)d_in[19];
  const float* enc0_b  = (const float*)d_in[20];
  const float* enc1_W  = (const float*)d_in[21];
  const float* enc1_b  = (const float*)d_in[22];
  const float* fc1_W   = (const float*)d_in[23];
  const float* fc1_b   = (const float*)d_in[24];
  const float* fc2_W   = (const float*)d_in[25];
  const float* fc2_b   = (const float*)d_in[26];
  float* out = (float*)d_out;

  float *p_t0, *p_h1, *p_h2, *p_bottom;
  cudaGetSymbolAddress((void**)&p_t0, g_t0);
  cudaGetSymbolAddress((void**)&p_h1, g_h1);
  cudaGetSymbolAddress((void**)&p_h2, g_h2);
  cudaGetSymbolAddress((void**)&p_bottom, g_bottom);

  cudaFuncSetAttribute(k_tf32gemm, cudaFuncAttributeMaxDynamicSharedMemorySize, GEMM_SMEM);

  static SideStream S;

  uint32_t kA0, kA1, kB0, kB1;
  tf2x32(0u, 42u, 0u, 0u, kA0, kA1);
  tf2x32(0u, 42u, 0u, 1u, kB0, kB1);

  dim3 g2(2, 125);

  // fork: preprocessing on side stream, concurrent with GEMM-1 on main
  cudaEventRecord(S.e1, 0);
  cudaStreamWaitEvent(S.s2, S.e1, 0);
  k_prep<<<63, 256, 0, S.s2>>>();
  k_hist<<<EE / 256, 256, 0, S.s2>>>(ei, ew);
  k_scan_dinv<<<1, 1024, 0, S.s2>>>();
  // main: GCN-1 dense (4th submission — profiled)
  k_tf32gemm<<<g2, 256, GEMM_SMEM>>>(x, nullptr, nullptr, FF, 0, 0, FF, 0, 0,
                                     conv1_W, HH, p_t0, HH, 0, nullptr);
  k_scatter<<<EE / 256, 256, 0, S.s2>>>(ei, ew);
  cudaEventRecord(S.e2, S.s2);

  // join before SpMM
  cudaStreamWaitEvent(0, S.e2, 0);
  k_spmm_ln_relu<<<NN, 256>>>(p_t0, p_h1, conv1_b, ln1_g, ln1_b);
  // GCN layer 2
  k_tf32gemm<<<g2, 256, GEMM_SMEM>>>(p_h1, nullptr, nullptr, HH, 0, 0, HH, 0, 0,
                                     conv2_W, HH, p_t0, HH, 0, nullptr);
  k_spmm_ln_relu<<<NN, 256>>>(p_t0, p_h2, conv2_b, ln2_g, ln2_b);

  // bottom = relu([x,h1,h2]@efc1 + b) @ efc2 + b   (fused 3-segment GEMM)
  k_tf32gemm<<<g2, 256, GEMM_SMEM>>>(x, p_h1, p_h2, FF, HH, HH, FF, HH, HH,
                                     efc1_W, HH, p_t0, HH, 2, efc1_b);
  k_tf32gemm<<<g2, 256, GEMM_SMEM>>>(p_t0, nullptr, nullptr, HH, 0, 0, HH, 0, 0,
                                     efc2_W, HH, p_bottom, HH, 1, efc2_b);
  cudaEventRecord(S.e3, 0);

  // pooling chain on side stream, concurrent with fc1 GEMM on main
  cudaStreamWaitEvent(S.s2, S.e3, 0);
  k_assign0<<<NN / 8, 256, 0, S.s2>>>(p_bottom, lin0_W, lin0_b, kA0, kA1);
  k_poolstats<<<NN / 64 + EE / 4096, 256, 0, S.s2>>>(ei);
  k_pool<<<1, 256, 0, S.s2>>>(enc0_W, enc0_b, lin1_W, lin1_b, enc1_W, enc1_b, fc1_W, kB0, kB1);
  cudaEventRecord(S.e4, S.s2);

  // fc1 mainloop (bias only; contrib folded into k_final)
  k_tf32gemm<<<g2, 256, GEMM_SMEM>>>(p_bottom, nullptr, nullptr, HH, 0, 0, HH, 0, 0,
                                     fc1_W, HH, p_t0, HH, 1, fc1_b);
  cudaStreamWaitEvent(0, S.e4, 0);
  k_final<<<NN / 8, 256>>>(p_t0, fc2_W, fc2_b, out);
}